// round 16
// baseline (speedup 1.0000x reference)
#include <cuda_runtime.h>
#include <cuda_fp16.h>
#include <cstdint>

#define BB 2
#define TT 2048
#define DD 1024
#define HH 16
#define DHH 64
#define NROWS (BB*TT)   // 4096

// Scratch (allocation-free rule: __device__ globals)
__device__ __half g_Qh[NROWS*DD];
__device__ __half g_Kh[NROWS*DD];
__device__ __half g_Vh[NROWS*DD];
__device__ __half g_xh[NROWS*DD];
__device__ __half g_Ah[NROWS*DD];
__device__ __half g_W[4*DD*DD];

// ---------------------------------------------------------------------------
// helpers (portable PTX: cp.async / ldmatrix / mma.sync)
// ---------------------------------------------------------------------------
__device__ __forceinline__ uint32_t smem_u32(const void* p) {
    uint32_t a;
    asm("{ .reg .u64 t; cvta.to.shared.u64 t, %1; cvt.u32.u64 %0, t; }" : "=r"(a) : "l"(p));
    return a;
}
__device__ __forceinline__ void cp16(uint32_t dst, const void* src) {
    asm volatile("cp.async.cg.shared.global [%0], [%1], 16;" :: "r"(dst), "l"(src));
}
#define CP_COMMIT() asm volatile("cp.async.commit_group;" ::: "memory")
#define CP_WAIT(n)  asm volatile("cp.async.wait_group %0;" :: "n"(n) : "memory")

__device__ __forceinline__ void ldm_x4(uint32_t* r, uint32_t addr) {
    asm volatile("ldmatrix.sync.aligned.m8n8.x4.shared.b16 {%0,%1,%2,%3}, [%4];"
                 : "=r"(r[0]), "=r"(r[1]), "=r"(r[2]), "=r"(r[3]) : "r"(addr));
}
__device__ __forceinline__ void ldm_x4_t(uint32_t* r, uint32_t addr) {
    asm volatile("ldmatrix.sync.aligned.m8n8.x4.trans.shared.b16 {%0,%1,%2,%3}, [%4];"
                 : "=r"(r[0]), "=r"(r[1]), "=r"(r[2]), "=r"(r[3]) : "r"(addr));
}
__device__ __forceinline__ void mma_f16(float* d, const uint32_t* a, uint32_t b0, uint32_t b1) {
    asm volatile(
        "mma.sync.aligned.m16n8k16.row.col.f32.f16.f16.f32 "
        "{%0,%1,%2,%3}, {%4,%5,%6,%7}, {%8,%9}, {%0,%1,%2,%3};"
        : "+f"(d[0]), "+f"(d[1]), "+f"(d[2]), "+f"(d[3])
        : "r"(a[0]), "r"(a[1]), "r"(a[2]), "r"(a[3]), "r"(b0), "r"(b1));
}
__device__ __forceinline__ uint32_t pack_f16(float lo, float hi) {
    __half2 t = __halves2half2(__float2half(lo), __float2half(hi));
    return *(uint32_t*)&t;
}

// ---------------------------------------------------------------------------
// one-shot conversion: x and all 4 weights -> fp16 (4-deep MLP per thread)
// ---------------------------------------------------------------------------
__global__ void __launch_bounds__(256) cvt_all(const float* __restrict__ x,
                                               const float* __restrict__ w0,
                                               const float* __restrict__ w1,
                                               const float* __restrict__ w2,
                                               const float* __restrict__ w3,
                                               __half* __restrict__ xh,
                                               __half* __restrict__ W) {
    const int XN4 = NROWS * DD / 4;        // 1M float4
    const int WN4 = DD * DD / 4;           // 256K float4
    const int N   = XN4 + 4 * WN4;         // 2M
    const int tid = blockIdx.x * blockDim.x + threadIdx.x;
    const int S   = gridDim.x * blockDim.x;

    int idx[4];
    float4 v[4];
    #pragma unroll
    for (int u = 0; u < 4; u++) idx[u] = tid + u * S;

    #pragma unroll
    for (int u = 0; u < 4; u++) {
        const int i = idx[u];
        if (i >= N) continue;
        const float* src;
        int j;
        if (i < XN4) { src = x; j = i; }
        else {
            const int t = i - XN4;
            const int m = t / WN4;
            j = t - m * WN4;
            src = (m == 0) ? w0 : (m == 1) ? w1 : (m == 2) ? w2 : w3;
        }
        v[u] = ((const float4*)src)[j];
    }
    #pragma unroll
    for (int u = 0; u < 4; u++) {
        const int i = idx[u];
        if (i >= N) continue;
        uint2* dst;
        int j;
        if (i < XN4) { dst = (uint2*)xh; j = i; }
        else {
            const int t = i - XN4;
            const int m = t / WN4;
            j = t - m * WN4;
            dst = (uint2*)W + (size_t)m * WN4;
        }
        __align__(8) __half h[4];
        h[0] = __float2half(v[u].x); h[1] = __float2half(v[u].y);
        h[2] = __float2half(v[u].z); h[3] = __float2half(v[u].w);
        dst[j] = *(const uint2*)h;
    }
}

// ---------------------------------------------------------------------------
// GEMM mainloop (champion config): C[n,m] = sum_k A[n,k]*B[m,k].
// CTA tile 128x256, BK=64, 512 threads (16 warps = 4m x 4n, warp tile 32x64).
// 4 smem buffers (48KB each: A 16KB +0, B 32KB +16384), depth-3 pipeline,
// one __syncthreads per stage. Rows 128B (8 chunks), swizzle cd^(r&7).
// Warp-staggered k16 order spreads LDS bursts under MMA.
// ---------------------------------------------------------------------------
#define NSTAGE 4
#define STG 49152
#define GEMM_SMEM (NSTAGE * STG)   // 192 KB

__device__ __forceinline__ void gemm_mainloop(
    const __half* __restrict__ Ag, const __half* __restrict__ Bg,
    int n0, int m0, uint32_t sbase, float acc[2][8][4]) {
    const int tid  = threadIdx.x;
    const int wid  = tid >> 5;
    const int lane = tid & 31;
    const int warp_m = (wid & 3) * 32;
    const int warp_n = (wid >> 2) * 64;
    const int KT = DD / 64;   // 16 stages

    const int lrow = tid >> 2;            // 0..127
    const int lc   = (tid & 3) * 2;       // chunk pair base 0,2,4,6
    auto soff = [](int r, int cd) { return (uint32_t)(r * 128 + ((cd ^ (r & 7)) << 4)); };

    auto load_stage = [&](int s) {
        const int k0 = s * 64;
        const uint32_t stg = sbase + (uint32_t)(s & (NSTAGE - 1)) * STG;
        #pragma unroll
        for (int i = 0; i < 2; i++) {
            const int cd = lc + i;
            cp16(stg + soff(lrow, cd), Ag + (size_t)(n0 + lrow) * DD + k0 + cd * 8);
        }
        #pragma unroll
        for (int rr = 0; rr < 2; rr++) {
            const int row = lrow + rr * 128;
            #pragma unroll
            for (int i = 0; i < 2; i++) {
                const int cd = lc + i;
                cp16(stg + 16384 + soff(row, cd), Bg + (size_t)(m0 + row) * DD + k0 + cd * 8);
            }
        }
        CP_COMMIT();
    };

    load_stage(0);
    load_stage(1);
    load_stage(2);

    #pragma unroll
    for (int mt = 0; mt < 2; mt++)
        #pragma unroll
        for (int nt = 0; nt < 8; nt++)
            #pragma unroll
            for (int i = 0; i < 4; i++) acc[mt][nt][i] = 0.0f;

    const int a_r    = (lane & 15);
    const int a_csel = (lane >> 4);
    const int b_g    = (lane >> 3);
    const int b_r    = ((b_g >> 1) << 3) + (lane & 7);
    const int b_csel = (b_g & 1);
    const int jrot   = wid & 3;     // stagger phase per warp

    for (int s = 0; s < KT; s++) {
        CP_WAIT(2);        // stage s resident
        __syncthreads();   // all warps past stage s-1 -> buf (s+3)&3 free
        if (s + 3 < KT) load_stage(s + 3);
        else            CP_COMMIT();

        const uint32_t stg = sbase + (uint32_t)(s & (NSTAGE - 1)) * STG;
        #pragma unroll
        for (int j = 0; j < 4; j++) {
            const int cbase = (((j + jrot) & 3) << 1);   // k16 step -> chunk base
            uint32_t af[2][4], bf[4][4];
            #pragma unroll
            for (int mt = 0; mt < 2; mt++) {
                const int r = warp_m + mt * 16 + a_r;
                ldm_x4(af[mt], stg + soff(r, cbase + a_csel));
            }
            #pragma unroll
            for (int ng = 0; ng < 4; ng++) {
                const int r = warp_n + ng * 16 + b_r;
                ldm_x4(bf[ng], stg + 16384 + soff(r, cbase + b_csel));
            }
            #pragma unroll
            for (int mt = 0; mt < 2; mt++)
                #pragma unroll
                for (int nt = 0; nt < 8; nt++) {
                    const uint32_t b0 = bf[nt >> 1][(nt & 1) * 2];
                    const uint32_t b1 = bf[nt >> 1][(nt & 1) * 2 + 1];
                    mma_f16(acc[mt][nt], af[mt], b0, b1);
                }
        }
    }
}

// fused Q/K/V projection: grid (12, 32); blockIdx.x>>2 selects Wq/Wk/Wv.
__global__ void __launch_bounds__(512, 1) gemm_qkv(
    const __half* __restrict__ xh, const __half* __restrict__ W,
    __half* __restrict__ Qh, __half* __restrict__ Kh, __half* __restrict__ Vh) {
    extern __shared__ __align__(128) char smem[];
    const int wsel = blockIdx.x >> 2;
    const int m0 = (blockIdx.x & 3) * 256;
    const int n0 = blockIdx.y * 128;

    float acc[2][8][4];
    gemm_mainloop(xh, W + (size_t)wsel * DD * DD, n0, m0, smem_u32(smem), acc);

    const int wid  = threadIdx.x >> 5;
    const int lane = threadIdx.x & 31;
    const int warp_m = (wid & 3) * 32;
    const int warp_n = (wid >> 2) * 64;

    __half* dst = (wsel == 0) ? Qh : (wsel == 1) ? Kh : Vh;

    #pragma unroll
    for (int mt = 0; mt < 2; mt++)
        #pragma unroll
        for (int nt = 0; nt < 8; nt++) {
            const int r   = n0 + warp_m + mt * 16 + (lane >> 2);
            const int col = m0 + warp_n + nt * 8 + (lane & 3) * 2;
            #pragma unroll
            for (int h2 = 0; h2 < 2; h2++) {
                const size_t o = (size_t)(r + 8 * h2) * DD + col;
                *(uint32_t*)(dst + o) = pack_f16(acc[mt][nt][2 * h2], acc[mt][nt][2 * h2 + 1]);
            }
        }
}

// output projection: grid (4, 32); fp32 out.
__global__ void __launch_bounds__(512, 1) gemm_out(
    const __half* __restrict__ Ah, const __half* __restrict__ W,
    float* __restrict__ out) {
    extern __shared__ __align__(128) char smem[];
    const int m0 = blockIdx.x * 256;
    const int n0 = blockIdx.y * 128;

    float acc[2][8][4];
    gemm_mainloop(Ah, W, n0, m0, smem_u32(smem), acc);

    const int wid  = threadIdx.x >> 5;
    const int lane = threadIdx.x & 31;
    const int warp_m = (wid & 3) * 32;
    const int warp_n = (wid >> 2) * 64;

    #pragma unroll
    for (int mt = 0; mt < 2; mt++)
        #pragma unroll
        for (int nt = 0; nt < 8; nt++) {
            const int r   = n0 + warp_m + mt * 16 + (lane >> 2);
            const int col = m0 + warp_n + nt * 8 + (lane & 3) * 2;
            float2 v0 = {acc[mt][nt][0], acc[mt][nt][1]};
            float2 v1 = {acc[mt][nt][2], acc[mt][nt][3]};
            *(float2*)(out + (size_t)r * DD + col)       = v0;
            *(float2*)(out + (size_t)(r + 8) * DD + col) = v1;
        }
}

// ---------------------------------------------------------------------------
// Tensor-core sliding-window flash attention (plain fp16 operands, fp32 acc).
// CTA: 128 queries x (b,h); 8 warps, warp = 16 queries x 64 keys.
// Per-warp chunk skipping: fully-masked warp-chunk pairs skip MMA work.
// smem: Q 16KB, then 2 bufs of (K 8K + V 8K). 48KB total; 2 CTAs/SM.
// ---------------------------------------------------------------------------
#define QTILE 128
#define ATTN_SMEM (16384 + 2*16384)

__global__ void __launch_bounds__(256, 2) attn_tc(
    const __half* __restrict__ Qh,
    const __half* __restrict__ Kh, const __half* __restrict__ Vh,
    __half* __restrict__ Ah) {
    extern __shared__ __align__(128) char smem[];
    const uint32_t sb = smem_u32(smem);
    const int tid = threadIdx.x;
    const int lane = tid & 31;
    const int w = tid >> 5;             // 0..7
    const int q0 = blockIdx.x * QTILE;
    const int h = blockIdx.y;
    const int b = blockIdx.z;
    const size_t rowbase = (size_t)b * TT;
    const int col0 = h * DHH;

    const uint32_t QH_ = sb;
    auto KV_ = [&](int buf) { return sb + 16384 + (uint32_t)buf * 16384; };

    auto toff = [](int r, int cd) { return (uint32_t)(r * 128 + ((cd ^ (r & 7)) << 4)); };

    // Q loader: 256 threads, rows 0..127, 4 chunks per thread
    const int qlr = tid >> 1;
    const int qlc = (tid & 1) * 4;
    auto load_q = [&]() {
        const size_t g = (rowbase + q0 + qlr) * DD + col0;
        #pragma unroll
        for (int c = 0; c < 4; c++) {
            const int cd = qlc + c;
            cp16(QH_ + toff(qlr, cd), Qh + g + cd * 8);
        }
    };
    // KV loader: 64 rows, 2 chunks per thread per array
    const int klr = tid >> 2;
    const int klc = (tid & 3) * 2;
    auto load_kv = [&](int c, int buf) {
        const size_t g = (rowbase + c * 64 + klr) * DD + col0;
        const uint32_t base = KV_(buf);
        #pragma unroll
        for (int cc = 0; cc < 2; cc++) {
            const int cd = klc + cc;
            const uint32_t d = toff(klr, cd);
            cp16(base + 0    + d, Kh + g + cd * 8);
            cp16(base + 8192 + d, Vh + g + cd * 8);
        }
    };

    const int c_lo = (q0 >= 128) ? ((q0 - 128) >> 6) : 0;
    const int c_hi = (q0 + QTILE - 1) >> 6;

    load_q();
    load_kv(c_lo, c_lo & 1);
    CP_COMMIT();

    float m[2] = {-1e30f, -1e30f}, l[2] = {0.0f, 0.0f};
    float accO[8][4];
    #pragma unroll
    for (int nt = 0; nt < 8; nt++)
        #pragma unroll
        for (int i = 0; i < 4; i++) accO[nt][i] = 0.0f;

    uint32_t qhf[4][4];
    bool qloaded = false;

    const int row_in_warp = lane >> 2;
    const int colpair = (lane & 3) * 2;
    const int wq0 = q0 + w * 16;        // warp's first query

    for (int c = c_lo; c <= c_hi; c++) {
        const int buf = c & 1;
        if (c < c_hi) { load_kv(c + 1, (c + 1) & 1); CP_COMMIT(); CP_WAIT(1); }
        else          { CP_WAIT(0); }
        __syncthreads();

        const int kbase = c * 64;
        // per-warp skip: warp window is keys [wq0-128, wq0+15]
        const bool active = (kbase + 63 >= wq0 - 128) && (kbase <= wq0 + 15);

        if (active) {
            if (!qloaded) {
                qloaded = true;
                #pragma unroll
                for (int ks = 0; ks < 4; ks++) {
                    const int r = w * 16 + (lane & 15);
                    const int cd = 2 * ks + (lane >> 4);
                    ldm_x4(qhf[ks], QH_ + toff(r, cd));
                }
            }

            // ---- S = Q K^T (fp16) ----
            float sacc[8][4];
            #pragma unroll
            for (int nt = 0; nt < 8; nt++)
                #pragma unroll
                for (int i = 0; i < 4; i++) sacc[nt][i] = 0.0f;

            const uint32_t kh_base = KV_(buf);
            const int krow = (lane & 7) + ((lane & 16) >> 1);
            const int kcd0 = (lane >> 3) & 1;
            #pragma unroll
            for (int ks = 0; ks < 4; ks++) {
                #pragma unroll
                for (int ng = 0; ng < 4; ng++) {
                    const int rn = ng * 16 + krow;
                    const int cd = 2 * ks + kcd0;
                    uint32_t bh[4];
                    ldm_x4(bh, kh_base + toff(rn, cd));
                    mma_f16(sacc[2*ng],   qhf[ks], bh[0], bh[1]);
                    mma_f16(sacc[2*ng+1], qhf[ks], bh[2], bh[3]);
                }
            }

            // ---- mask + scale + online softmax ----
            float rmax[2] = {-1e30f, -1e30f};
            #pragma unroll
            for (int nt = 0; nt < 8; nt++)
                #pragma unroll
                for (int e2 = 0; e2 < 4; e2++) {
                    const int h2 = e2 >> 1;
                    const int key = kbase + nt * 8 + colpair + (e2 & 1);
                    const int iq  = wq0 + row_in_warp + 8 * h2;
                    float s = sacc[nt][e2] * 0.125f;
                    s = (key <= iq && key + 128 >= iq) ? s : -1e30f;
                    sacc[nt][e2] = s;
                    rmax[h2] = fmaxf(rmax[h2], s);
                }
            #pragma unroll
            for (int h2 = 0; h2 < 2; h2++) {
                rmax[h2] = fmaxf(rmax[h2], __shfl_xor_sync(0xffffffffu, rmax[h2], 1));
                rmax[h2] = fmaxf(rmax[h2], __shfl_xor_sync(0xffffffffu, rmax[h2], 2));
            }
            float corr[2], rsum[2] = {0.0f, 0.0f};
            #pragma unroll
            for (int h2 = 0; h2 < 2; h2++) {
                const float newm = fmaxf(m[h2], rmax[h2]);
                corr[h2] = __expf(m[h2] - newm);
                m[h2] = newm;
            }
            #pragma unroll
            for (int nt = 0; nt < 8; nt++)
                #pragma unroll
                for (int e2 = 0; e2 < 4; e2++) {
                    const int h2 = e2 >> 1;
                    const float p = __expf(sacc[nt][e2] - m[h2]);
                    sacc[nt][e2] = p;
                    rsum[h2] += p;
                }
            #pragma unroll
            for (int h2 = 0; h2 < 2; h2++) {
                rsum[h2] += __shfl_xor_sync(0xffffffffu, rsum[h2], 1);
                rsum[h2] += __shfl_xor_sync(0xffffffffu, rsum[h2], 2);
                l[h2] = l[h2] * corr[h2] + rsum[h2];
            }
            #pragma unroll
            for (int nt = 0; nt < 8; nt++) {
                accO[nt][0] *= corr[0]; accO[nt][1] *= corr[0];
                accO[nt][2] *= corr[1]; accO[nt][3] *= corr[1];
            }

            // ---- P fragments (registers, plain fp16) ----
            uint32_t ph[4][4];
            #pragma unroll
            for (int js = 0; js < 4; js++) {
                #pragma unroll
                for (int half16 = 0; half16 < 2; half16++) {
                    const int nt = 2 * js + half16;
                    #pragma unroll
                    for (int h2 = 0; h2 < 2; h2++) {
                        ph[js][half16 * 2 + h2] = pack_f16(sacc[nt][2 * h2], sacc[nt][2 * h2 + 1]);
                    }
                }
            }

            // ---- O += P V (fp16, V via ldmatrix.trans) ----
            const uint32_t vh_base = KV_(buf) + 8192;
            const int vrow = (lane & 7) + (lane & 8);
            const int vcd0 = lane >> 4;
            #pragma unroll
            for (int js = 0; js < 4; js++) {
                #pragma unroll
                for (int ng = 0; ng < 4; ng++) {
                    const int rv = js * 16 + vrow;
                    const int cd = 2 * ng + vcd0;
                    uint32_t vhf[4];
                    ldm_x4_t(vhf, vh_base + toff(rv, cd));
                    mma_f16(accO[2*ng],   ph[js], vhf[0], vhf[1]);
                    mma_f16(accO[2*ng+1], ph[js], vhf[2], vhf[3]);
                }
            }
        }
        __syncthreads();
    }

    // ---- write O (single fp16) ----
    const float inv0 = 1.0f / l[0], inv1 = 1.0f / l[1];
    #pragma unroll
    for (int nt = 0; nt < 8; nt++) {
        #pragma unroll
        for (int h2 = 0; h2 < 2; h2++) {
            const float inv = h2 ? inv1 : inv0;
            const int gi = wq0 + row_in_warp + 8 * h2;
            const size_t o = (rowbase + gi) * DD + col0 + nt * 8 + colpair;
            *(uint32_t*)(Ah + o) = pack_f16(accO[nt][2 * h2] * inv,
                                            accO[nt][2 * h2 + 1] * inv);
        }
    }
}

// ---------------------------------------------------------------------------
extern "C" void kernel_launch(void* const* d_in, const int* in_sizes, int n_in,
                              void* d_out, int out_size) {
    const float* x  = (const float*)d_in[0];
    const float* Wq = (const float*)d_in[1];
    const float* Wk = (const float*)d_in[2];
    const float* Wv = (const float*)d_in[3];
    const float* Wo = (const float*)d_in[4];
    float* out = (float*)d_out;

    __half *Qh, *Kh, *Vh, *xh, *Ah, *W;
    cudaGetSymbolAddress((void**)&Qh, g_Qh);
    cudaGetSymbolAddress((void**)&Kh, g_Kh);
    cudaGetSymbolAddress((void**)&Vh, g_Vh);
    cudaGetSymbolAddress((void**)&xh, g_xh);
    cudaGetSymbolAddress((void**)&Ah, g_Ah);
    cudaGetSymbolAddress((void**)&W,  g_W);

    static bool attr_done = false;
    if (!attr_done) {
        cudaFuncSetAttribute(gemm_qkv, cudaFuncAttributeMaxDynamicSharedMemorySize, GEMM_SMEM);
        cudaFuncSetAttribute(gemm_out, cudaFuncAttributeMaxDynamicSharedMemorySize, GEMM_SMEM);
        cudaFuncSetAttribute(attn_tc, cudaFuncAttributeMaxDynamicSharedMemorySize, ATTN_SMEM);
        attr_done = true;
    }

    const int CVT_N = NROWS * DD / 4 + DD * DD;   // 2M float4
    cvt_all<<<(CVT_N / 4 + 255) / 256, 256>>>(x, Wq, Wk, Wv, Wo, xh, W);

    gemm_qkv<<<dim3(12, 32), 512, GEMM_SMEM>>>(xh, W, Qh, Kh, Vh);

    attn_tc<<<dim3(TT / QTILE, HH, BB), 256, ATTN_SMEM>>>(Qh, Kh, Vh, Ah);

    gemm_out<<<dim3(4, 32), 512, GEMM_SMEM>>>(Ah, W + 3 * (size_t)DD * DD, out);
}

// round 17
// speedup vs baseline: 1.0156x; 1.0156x over previous
#include <cuda_runtime.h>
#include <cuda_fp16.h>
#include <cstdint>

#define BB 2
#define TT 2048
#define DD 1024
#define HH 16
#define DHH 64
#define NROWS (BB*TT)   // 4096

// Scratch (allocation-free rule: __device__ globals)
__device__ __half g_Qh[NROWS*DD];
__device__ __half g_Kh[NROWS*DD];
__device__ __half g_Vh[NROWS*DD];
__device__ __half g_xh[NROWS*DD];
__device__ __half g_Ah[NROWS*DD];
__device__ __half g_W[4*DD*DD];

// ---------------------------------------------------------------------------
// helpers (portable PTX: cp.async / ldmatrix / mma.sync)
// ---------------------------------------------------------------------------
__device__ __forceinline__ uint32_t smem_u32(const void* p) {
    uint32_t a;
    asm("{ .reg .u64 t; cvta.to.shared.u64 t, %1; cvt.u32.u64 %0, t; }" : "=r"(a) : "l"(p));
    return a;
}
__device__ __forceinline__ void cp16(uint32_t dst, const void* src) {
    asm volatile("cp.async.cg.shared.global [%0], [%1], 16;" :: "r"(dst), "l"(src));
}
#define CP_COMMIT() asm volatile("cp.async.commit_group;" ::: "memory")
#define CP_WAIT(n)  asm volatile("cp.async.wait_group %0;" :: "n"(n) : "memory")

__device__ __forceinline__ void ldm_x4(uint32_t* r, uint32_t addr) {
    asm volatile("ldmatrix.sync.aligned.m8n8.x4.shared.b16 {%0,%1,%2,%3}, [%4];"
                 : "=r"(r[0]), "=r"(r[1]), "=r"(r[2]), "=r"(r[3]) : "r"(addr));
}
__device__ __forceinline__ void ldm_x4_t(uint32_t* r, uint32_t addr) {
    asm volatile("ldmatrix.sync.aligned.m8n8.x4.trans.shared.b16 {%0,%1,%2,%3}, [%4];"
                 : "=r"(r[0]), "=r"(r[1]), "=r"(r[2]), "=r"(r[3]) : "r"(addr));
}
__device__ __forceinline__ void mma_f16(float* d, const uint32_t* a, uint32_t b0, uint32_t b1) {
    asm volatile(
        "mma.sync.aligned.m16n8k16.row.col.f32.f16.f16.f32 "
        "{%0,%1,%2,%3}, {%4,%5,%6,%7}, {%8,%9}, {%0,%1,%2,%3};"
        : "+f"(d[0]), "+f"(d[1]), "+f"(d[2]), "+f"(d[3])
        : "r"(a[0]), "r"(a[1]), "r"(a[2]), "r"(a[3]), "r"(b0), "r"(b1));
}
__device__ __forceinline__ uint32_t pack_f16(float lo, float hi) {
    __half2 t = __halves2half2(__float2half(lo), __float2half(hi));
    return *(uint32_t*)&t;
}

// ---------------------------------------------------------------------------
// one-shot conversion: x and all 4 weights -> fp16 (4-deep MLP per thread)
// ---------------------------------------------------------------------------
__global__ void __launch_bounds__(256) cvt_all(const float* __restrict__ x,
                                               const float* __restrict__ w0,
                                               const float* __restrict__ w1,
                                               const float* __restrict__ w2,
                                               const float* __restrict__ w3,
                                               __half* __restrict__ xh,
                                               __half* __restrict__ W) {
    const int XN4 = NROWS * DD / 4;        // 1M float4
    const int WN4 = DD * DD / 4;           // 256K float4
    const int N   = XN4 + 4 * WN4;         // 2M
    const int tid = blockIdx.x * blockDim.x + threadIdx.x;
    const int S   = gridDim.x * blockDim.x;

    int idx[4];
    float4 v[4];
    #pragma unroll
    for (int u = 0; u < 4; u++) idx[u] = tid + u * S;

    #pragma unroll
    for (int u = 0; u < 4; u++) {
        const int i = idx[u];
        if (i >= N) continue;
        const float* src;
        int j;
        if (i < XN4) { src = x; j = i; }
        else {
            const int t = i - XN4;
            const int m = t / WN4;
            j = t - m * WN4;
            src = (m == 0) ? w0 : (m == 1) ? w1 : (m == 2) ? w2 : w3;
        }
        v[u] = ((const float4*)src)[j];
    }
    #pragma unroll
    for (int u = 0; u < 4; u++) {
        const int i = idx[u];
        if (i >= N) continue;
        uint2* dst;
        int j;
        if (i < XN4) { dst = (uint2*)xh; j = i; }
        else {
            const int t = i - XN4;
            const int m = t / WN4;
            j = t - m * WN4;
            dst = (uint2*)W + (size_t)m * WN4;
        }
        __align__(8) __half h[4];
        h[0] = __float2half(v[u].x); h[1] = __float2half(v[u].y);
        h[2] = __float2half(v[u].z); h[3] = __float2half(v[u].w);
        dst[j] = *(const uint2*)h;
    }
}

// ---------------------------------------------------------------------------
// GEMM mainloop (champion config): C[n,m] = sum_k A[n,k]*B[m,k].
// CTA tile 128x256, BK=64, 512 threads (16 warps = 4m x 4n, warp tile 32x64).
// 4 smem buffers (48KB each: A 16KB +0, B 32KB +16384), depth-3 pipeline,
// one __syncthreads per stage. Rows 128B (8 chunks), swizzle cd^(r&7).
// Warp-staggered k16 order spreads LDS bursts under MMA.
// ---------------------------------------------------------------------------
#define NSTAGE 4
#define STG 49152
#define GEMM_SMEM (NSTAGE * STG)   // 192 KB

__device__ __forceinline__ void gemm_mainloop(
    const __half* __restrict__ Ag, const __half* __restrict__ Bg,
    int n0, int m0, uint32_t sbase, float acc[2][8][4]) {
    const int tid  = threadIdx.x;
    const int wid  = tid >> 5;
    const int lane = tid & 31;
    const int warp_m = (wid & 3) * 32;
    const int warp_n = (wid >> 2) * 64;
    const int KT = DD / 64;   // 16 stages

    const int lrow = tid >> 2;            // 0..127
    const int lc   = (tid & 3) * 2;       // chunk pair base 0,2,4,6
    auto soff = [](int r, int cd) { return (uint32_t)(r * 128 + ((cd ^ (r & 7)) << 4)); };

    auto load_stage = [&](int s) {
        const int k0 = s * 64;
        const uint32_t stg = sbase + (uint32_t)(s & (NSTAGE - 1)) * STG;
        #pragma unroll
        for (int i = 0; i < 2; i++) {
            const int cd = lc + i;
            cp16(stg + soff(lrow, cd), Ag + (size_t)(n0 + lrow) * DD + k0 + cd * 8);
        }
        #pragma unroll
        for (int rr = 0; rr < 2; rr++) {
            const int row = lrow + rr * 128;
            #pragma unroll
            for (int i = 0; i < 2; i++) {
                const int cd = lc + i;
                cp16(stg + 16384 + soff(row, cd), Bg + (size_t)(m0 + row) * DD + k0 + cd * 8);
            }
        }
        CP_COMMIT();
    };

    load_stage(0);
    load_stage(1);
    load_stage(2);

    #pragma unroll
    for (int mt = 0; mt < 2; mt++)
        #pragma unroll
        for (int nt = 0; nt < 8; nt++)
            #pragma unroll
            for (int i = 0; i < 4; i++) acc[mt][nt][i] = 0.0f;

    const int a_r    = (lane & 15);
    const int a_csel = (lane >> 4);
    const int b_g    = (lane >> 3);
    const int b_r    = ((b_g >> 1) << 3) + (lane & 7);
    const int b_csel = (b_g & 1);
    const int jrot   = wid & 3;     // stagger phase per warp

    for (int s = 0; s < KT; s++) {
        CP_WAIT(2);        // stage s resident
        __syncthreads();   // all warps past stage s-1 -> buf (s+3)&3 free
        if (s + 3 < KT) load_stage(s + 3);
        else            CP_COMMIT();

        const uint32_t stg = sbase + (uint32_t)(s & (NSTAGE - 1)) * STG;
        #pragma unroll
        for (int j = 0; j < 4; j++) {
            const int cbase = (((j + jrot) & 3) << 1);   // k16 step -> chunk base
            uint32_t af[2][4], bf[4][4];
            #pragma unroll
            for (int mt = 0; mt < 2; mt++) {
                const int r = warp_m + mt * 16 + a_r;
                ldm_x4(af[mt], stg + soff(r, cbase + a_csel));
            }
            #pragma unroll
            for (int ng = 0; ng < 4; ng++) {
                const int r = warp_n + ng * 16 + b_r;
                ldm_x4(bf[ng], stg + 16384 + soff(r, cbase + b_csel));
            }
            #pragma unroll
            for (int mt = 0; mt < 2; mt++)
                #pragma unroll
                for (int nt = 0; nt < 8; nt++) {
                    const uint32_t b0 = bf[nt >> 1][(nt & 1) * 2];
                    const uint32_t b1 = bf[nt >> 1][(nt & 1) * 2 + 1];
                    mma_f16(acc[mt][nt], af[mt], b0, b1);
                }
        }
    }
}

// fused Q/K/V projection: grid (12, 32); blockIdx.x>>2 selects Wq/Wk/Wv.
__global__ void __launch_bounds__(512, 1) gemm_qkv(
    const __half* __restrict__ xh, const __half* __restrict__ W,
    __half* __restrict__ Qh, __half* __restrict__ Kh, __half* __restrict__ Vh) {
    extern __shared__ __align__(128) char smem[];
    const int wsel = blockIdx.x >> 2;
    const int m0 = (blockIdx.x & 3) * 256;
    const int n0 = blockIdx.y * 128;

    float acc[2][8][4];
    gemm_mainloop(xh, W + (size_t)wsel * DD * DD, n0, m0, smem_u32(smem), acc);

    const int wid  = threadIdx.x >> 5;
    const int lane = threadIdx.x & 31;
    const int warp_m = (wid & 3) * 32;
    const int warp_n = (wid >> 2) * 64;

    __half* dst = (wsel == 0) ? Qh : (wsel == 1) ? Kh : Vh;

    #pragma unroll
    for (int mt = 0; mt < 2; mt++)
        #pragma unroll
        for (int nt = 0; nt < 8; nt++) {
            const int r   = n0 + warp_m + mt * 16 + (lane >> 2);
            const int col = m0 + warp_n + nt * 8 + (lane & 3) * 2;
            #pragma unroll
            for (int h2 = 0; h2 < 2; h2++) {
                const size_t o = (size_t)(r + 8 * h2) * DD + col;
                *(uint32_t*)(dst + o) = pack_f16(acc[mt][nt][2 * h2], acc[mt][nt][2 * h2 + 1]);
            }
        }
}

// output projection: grid (4, 32); fp32 out.
__global__ void __launch_bounds__(512, 1) gemm_out(
    const __half* __restrict__ Ah, const __half* __restrict__ W,
    float* __restrict__ out) {
    extern __shared__ __align__(128) char smem[];
    const int m0 = blockIdx.x * 256;
    const int n0 = blockIdx.y * 128;

    float acc[2][8][4];
    gemm_mainloop(Ah, W, n0, m0, smem_u32(smem), acc);

    const int wid  = threadIdx.x >> 5;
    const int lane = threadIdx.x & 31;
    const int warp_m = (wid & 3) * 32;
    const int warp_n = (wid >> 2) * 64;

    #pragma unroll
    for (int mt = 0; mt < 2; mt++)
        #pragma unroll
        for (int nt = 0; nt < 8; nt++) {
            const int r   = n0 + warp_m + mt * 16 + (lane >> 2);
            const int col = m0 + warp_n + nt * 8 + (lane & 3) * 2;
            float2 v0 = {acc[mt][nt][0], acc[mt][nt][1]};
            float2 v1 = {acc[mt][nt][2], acc[mt][nt][3]};
            *(float2*)(out + (size_t)r * DD + col)       = v0;
            *(float2*)(out + (size_t)(r + 8) * DD + col) = v1;
        }
}

// ---------------------------------------------------------------------------
// Tensor-core sliding-window flash attention (plain fp16 operands, fp32 acc).
// CTA: 64 queries x (b,h); 4 warps, warp = 16 queries x 64 keys.
// smem: Q 8KB, then 2 bufs of (K 8K + V 8K). 40KB total; 3 CTAs/SM.
// ---------------------------------------------------------------------------
#define ATTN_SMEM (8192 + 2*16384)

__global__ void __launch_bounds__(128, 3) attn_tc(
    const __half* __restrict__ Qh,
    const __half* __restrict__ Kh, const __half* __restrict__ Vh,
    __half* __restrict__ Ah) {
    extern __shared__ __align__(128) char smem[];
    const uint32_t sb = smem_u32(smem);
    const int tid = threadIdx.x;
    const int lane = tid & 31;
    const int w = tid >> 5;
    const int q0 = blockIdx.x * 64;
    const int h = blockIdx.y;
    const int b = blockIdx.z;
    const size_t rowbase = (size_t)b * TT;
    const int col0 = h * DHH;

    const uint32_t QH_ = sb;
    auto KV_ = [&](int buf) { return sb + 8192 + (uint32_t)buf * 16384; };

    auto toff = [](int r, int cd) { return (uint32_t)(r * 128 + ((cd ^ (r & 7)) << 4)); };

    const int lr = tid >> 1;
    const int lc0 = (tid & 1) * 4;
    auto load_q = [&]() {
        const size_t g = (rowbase + q0 + lr) * DD + col0;
        #pragma unroll
        for (int c = 0; c < 4; c++) {
            const int cd = lc0 + c;
            cp16(QH_ + toff(lr, cd), Qh + g + cd * 8);
        }
    };
    auto load_kv = [&](int c, int buf) {
        const size_t g = (rowbase + c * 64 + lr) * DD + col0;
        const uint32_t base = KV_(buf);
        #pragma unroll
        for (int cc = 0; cc < 4; cc++) {
            const int cd = lc0 + cc;
            const uint32_t d = toff(lr, cd);
            cp16(base + 0    + d, Kh + g + cd * 8);
            cp16(base + 8192 + d, Vh + g + cd * 8);
        }
    };

    const int c_lo = (q0 >= 128) ? ((q0 - 128) >> 6) : 0;
    const int c_hi = q0 >> 6;

    load_q();
    load_kv(c_lo, c_lo & 1);
    CP_COMMIT();

    float m[2] = {-1e30f, -1e30f}, l[2] = {0.0f, 0.0f};
    float accO[8][4];
    #pragma unroll
    for (int nt = 0; nt < 8; nt++)
        #pragma unroll
        for (int i = 0; i < 4; i++) accO[nt][i] = 0.0f;

    uint32_t qhf[4][4];
    bool qloaded = false;

    const int row_in_warp = lane >> 2;
    const int colpair = (lane & 3) * 2;

    for (int c = c_lo; c <= c_hi; c++) {
        const int buf = c & 1;
        if (c < c_hi) { load_kv(c + 1, (c + 1) & 1); CP_COMMIT(); CP_WAIT(1); }
        else          { CP_WAIT(0); }
        __syncthreads();

        if (!qloaded) {
            qloaded = true;
            #pragma unroll
            for (int ks = 0; ks < 4; ks++) {
                const int r = w * 16 + (lane & 15);
                const int cd = 2 * ks + (lane >> 4);
                ldm_x4(qhf[ks], QH_ + toff(r, cd));
            }
        }

        // ---- S = Q K^T (fp16) ----
        float sacc[8][4];
        #pragma unroll
        for (int nt = 0; nt < 8; nt++)
            #pragma unroll
            for (int i = 0; i < 4; i++) sacc[nt][i] = 0.0f;

        const uint32_t kh_base = KV_(buf);
        const int krow = (lane & 7) + ((lane & 16) >> 1);
        const int kcd0 = (lane >> 3) & 1;
        #pragma unroll
        for (int ks = 0; ks < 4; ks++) {
            #pragma unroll
            for (int ng = 0; ng < 4; ng++) {
                const int rn = ng * 16 + krow;
                const int cd = 2 * ks + kcd0;
                uint32_t bh[4];
                ldm_x4(bh, kh_base + toff(rn, cd));
                mma_f16(sacc[2*ng],   qhf[ks], bh[0], bh[1]);
                mma_f16(sacc[2*ng+1], qhf[ks], bh[2], bh[3]);
            }
        }

        // ---- mask + scale + online softmax ----
        const int kbase = c * 64;
        float rmax[2] = {-1e30f, -1e30f};
        #pragma unroll
        for (int nt = 0; nt < 8; nt++)
            #pragma unroll
            for (int e2 = 0; e2 < 4; e2++) {
                const int h2 = e2 >> 1;
                const int key = kbase + nt * 8 + colpair + (e2 & 1);
                const int iq  = q0 + w * 16 + row_in_warp + 8 * h2;
                float s = sacc[nt][e2] * 0.125f;
                s = (key <= iq && key + 128 >= iq) ? s : -1e30f;
                sacc[nt][e2] = s;
                rmax[h2] = fmaxf(rmax[h2], s);
            }
        #pragma unroll
        for (int h2 = 0; h2 < 2; h2++) {
            rmax[h2] = fmaxf(rmax[h2], __shfl_xor_sync(0xffffffffu, rmax[h2], 1));
            rmax[h2] = fmaxf(rmax[h2], __shfl_xor_sync(0xffffffffu, rmax[h2], 2));
        }
        float corr[2], rsum[2] = {0.0f, 0.0f};
        #pragma unroll
        for (int h2 = 0; h2 < 2; h2++) {
            const float newm = fmaxf(m[h2], rmax[h2]);
            corr[h2] = __expf(m[h2] - newm);
            m[h2] = newm;
        }
        #pragma unroll
        for (int nt = 0; nt < 8; nt++)
            #pragma unroll
            for (int e2 = 0; e2 < 4; e2++) {
                const int h2 = e2 >> 1;
                const float p = __expf(sacc[nt][e2] - m[h2]);
                sacc[nt][e2] = p;
                rsum[h2] += p;
            }
        #pragma unroll
        for (int h2 = 0; h2 < 2; h2++) {
            rsum[h2] += __shfl_xor_sync(0xffffffffu, rsum[h2], 1);
            rsum[h2] += __shfl_xor_sync(0xffffffffu, rsum[h2], 2);
            l[h2] = l[h2] * corr[h2] + rsum[h2];
        }
        #pragma unroll
        for (int nt = 0; nt < 8; nt++) {
            accO[nt][0] *= corr[0]; accO[nt][1] *= corr[0];
            accO[nt][2] *= corr[1]; accO[nt][3] *= corr[1];
        }

        // ---- P fragments (registers, plain fp16) ----
        uint32_t ph[4][4];
        #pragma unroll
        for (int js = 0; js < 4; js++) {
            #pragma unroll
            for (int half16 = 0; half16 < 2; half16++) {
                const int nt = 2 * js + half16;
                #pragma unroll
                for (int h2 = 0; h2 < 2; h2++) {
                    ph[js][half16 * 2 + h2] = pack_f16(sacc[nt][2 * h2], sacc[nt][2 * h2 + 1]);
                }
            }
        }

        // ---- O += P V (fp16, V via ldmatrix.trans) ----
        const uint32_t vh_base = KV_(buf) + 8192;
        const int vrow = (lane & 7) + (lane & 8);
        const int vcd0 = lane >> 4;
        #pragma unroll
        for (int js = 0; js < 4; js++) {
            #pragma unroll
            for (int ng = 0; ng < 4; ng++) {
                const int rv = js * 16 + vrow;
                const int cd = 2 * ng + vcd0;
                uint32_t vhf[4];
                ldm_x4_t(vhf, vh_base + toff(rv, cd));
                mma_f16(accO[2*ng],   ph[js], vhf[0], vhf[1]);
                mma_f16(accO[2*ng+1], ph[js], vhf[2], vhf[3]);
            }
        }
        __syncthreads();
    }

    // ---- write O (single fp16) ----
    const float inv0 = 1.0f / l[0], inv1 = 1.0f / l[1];
    #pragma unroll
    for (int nt = 0; nt < 8; nt++) {
        #pragma unroll
        for (int h2 = 0; h2 < 2; h2++) {
            const float inv = h2 ? inv1 : inv0;
            const int gi = q0 + w * 16 + row_in_warp + 8 * h2;
            const size_t o = (rowbase + gi) * DD + col0 + nt * 8 + colpair;
            *(uint32_t*)(Ah + o) = pack_f16(accO[nt][2 * h2] * inv,
                                            accO[nt][2 * h2 + 1] * inv);
        }
    }
}

// ---------------------------------------------------------------------------
extern "C" void kernel_launch(void* const* d_in, const int* in_sizes, int n_in,
                              void* d_out, int out_size) {
    const float* x  = (const float*)d_in[0];
    const float* Wq = (const float*)d_in[1];
    const float* Wk = (const float*)d_in[2];
    const float* Wv = (const float*)d_in[3];
    const float* Wo = (const float*)d_in[4];
    float* out = (float*)d_out;

    __half *Qh, *Kh, *Vh, *xh, *Ah, *W;
    cudaGetSymbolAddress((void**)&Qh, g_Qh);
    cudaGetSymbolAddress((void**)&Kh, g_Kh);
    cudaGetSymbolAddress((void**)&Vh, g_Vh);
    cudaGetSymbolAddress((void**)&xh, g_xh);
    cudaGetSymbolAddress((void**)&Ah, g_Ah);
    cudaGetSymbolAddress((void**)&W,  g_W);

    static bool attr_done = false;
    if (!attr_done) {
        cudaFuncSetAttribute(gemm_qkv, cudaFuncAttributeMaxDynamicSharedMemorySize, GEMM_SMEM);
        cudaFuncSetAttribute(gemm_out, cudaFuncAttributeMaxDynamicSharedMemorySize, GEMM_SMEM);
        cudaFuncSetAttribute(attn_tc, cudaFuncAttributeMaxDynamicSharedMemorySize, ATTN_SMEM);
        attr_done = true;
    }

    const int CVT_N = NROWS * DD / 4 + DD * DD;   // 2M float4
    cvt_all<<<(CVT_N / 4 + 255) / 256, 256>>>(x, Wq, Wk, Wv, Wo, xh, W);

    gemm_qkv<<<dim3(12, 32), 512, GEMM_SMEM>>>(xh, W, Qh, Kh, Vh);

    attn_tc<<<dim3(TT / 64, HH, BB), 128, ATTN_SMEM>>>(Qh, Kh, Vh, Ah);

    gemm_out<<<dim3(4, 32), 512, GEMM_SMEM>>>(Ah, W + 3 * (size_t)DD * DD, out);
}